// round 2
// baseline (speedup 1.0000x reference)
#include <cuda_runtime.h>
#include <cstdint>

#define BATCH 8192
#define NT1 256
#define NT2 128

typedef unsigned long long ull;

__device__ int   g_off[BATCH + 1];
__device__ float g_P[BATCH * 384];

__device__ __forceinline__ void fma2(ull& acc, ull a, ull b) {
    asm("fma.rn.f32x2 %0, %1, %2, %0;" : "+l"(acc) : "l"(a), "l"(b));
}

union F2U { ull u; float2 f; };

// ---------------- exclusive scan of sizes ----------------
__global__ void k_scan(const int* __restrict__ sizes) {
    __shared__ int part[1024];
    int tid = threadIdx.x;
    int base = tid * 8;
    int pref[8];
    int s = 0;
#pragma unroll
    for (int r = 0; r < 8; r++) { pref[r] = s; s += sizes[base + r]; }
    part[tid] = s;
    __syncthreads();
    for (int off = 1; off < 1024; off <<= 1) {
        int v = (tid >= off) ? part[tid - off] : 0;
        __syncthreads();
        part[tid] += v;
        __syncthreads();
    }
    int excl = (tid > 0) ? part[tid - 1] : 0;
#pragma unroll
    for (int r = 0; r < 8; r++) g_off[base + r] = excl + pref[r];
    if (tid == 1023) g_off[BATCH] = part[1023];
}

// ---------------- conv + segment maxpool ----------------
// One CTA = (segment, part). Parts: w=1 (128 m), w=2 (128 m), w=3 split into two
// 64-m halves so weights fit SMEM. Thread = (m, t-parallel slot). Register tile:
// 8 time positions, channel pairs packed into FFMA2 (even/odd sub-accumulators).
template<int W, int MCNT>
__device__ __forceinline__ void conv_part(
    const float* __restrict__ x, const float* __restrict__ cw,
    const float* __restrict__ cb, int mbase, int colbase, float* smem)
{
    const int RS   = W * 128 + 4;   // padded row stride: RS % 32 == 4 -> conflict-free LDS.128
    const int TPAR = NT1 / MCNT;
    float* xs = smem;               // [70][128]
    float* ws = smem + 70 * 128;    // [MCNT][RS]
    int tid = threadIdx.x;
    int seg = blockIdx.y;
    int off = g_off[seg];
    int S   = g_off[seg + 1] - off;

    // stage weights: global [m][c][j] -> smem ws[m][j*128 + c]
    const int WE = MCNT * 128 * W;
    const float* cwp = cw + (size_t)mbase * 128 * W;
    for (int idx = tid; idx < WE; idx += NT1) {
        int m = idx / (128 * W);
        int r = idx - m * (128 * W);
        int c = r / W;
        int j = r - c * W;
        ws[m * RS + j * 128 + c] = cwp[idx];
    }
    // stage x segment (rows >= S zeroed so padded tiles stay finite)
    const float* xp = x + (size_t)off * 128;
    int XE = S * 128;
    for (int idx = tid; idx < 70 * 128; idx += NT1)
        xs[idx] = (idx < XE) ? xp[idx] : 0.0f;
    __syncthreads();

    int m  = tid % MCNT;
    int tp = tid / MCNT;
    int L  = S - W + 1;             // valid positions (>= 14 since S >= 16)
    int nblk = (L + 7) >> 3;
    float mx = -3.0e38f;

    for (int b = tp; b < nblk; b += TPAR) {
        int t0 = b << 3;
        ull a01[8], a23[8];
#pragma unroll
        for (int t = 0; t < 8; t++) { a01[t] = 0ull; a23[t] = 0ull; }
        for (int c4 = 0; c4 < 128; c4 += 4) {
            ulonglong2 xb[8 + W - 1];
#pragma unroll
            for (int r = 0; r < 8 + W - 1; r++)
                xb[r] = *(const ulonglong2*)&xs[(t0 + r) * 128 + c4];
#pragma unroll
            for (int j = 0; j < W; j++) {
                ulonglong2 wv = *(const ulonglong2*)&ws[m * RS + j * 128 + c4];
#pragma unroll
                for (int t = 0; t < 8; t++) {
                    fma2(a01[t], xb[t + j].x, wv.x);
                    fma2(a23[t], xb[t + j].y, wv.y);
                }
            }
        }
#pragma unroll
        for (int t = 0; t < 8; t++) {
            if (t0 + t < L) {
                F2U u0, u1; u0.u = a01[t]; u1.u = a23[t];
                float h = (u0.f.x + u0.f.y) + (u1.f.x + u1.f.y);
                mx = fmaxf(mx, h);
            }
        }
    }

    __syncthreads();                // xs no longer needed; reuse as reduce buffer
    float* red = smem;
    red[tid] = mx;
    __syncthreads();
#pragma unroll
    for (int k = TPAR >> 1; k > 0; k >>= 1) {
        if (tp < k) red[tid] = fmaxf(red[tid], red[tid + k * MCNT]);
        __syncthreads();
    }
    if (tp == 0) {
        float v = fmaxf(0.0f, red[tid] + cb[mbase + m]);
        g_P[(size_t)seg * 384 + colbase + m] = v;
    }
}

__global__ void __launch_bounds__(NT1, 1) k_conv(
    const float* __restrict__ x,
    const float* __restrict__ w0, const float* __restrict__ b0,
    const float* __restrict__ w1, const float* __restrict__ b1,
    const float* __restrict__ w2, const float* __restrict__ b2)
{
    extern __shared__ float smem[];
    switch (blockIdx.x) {
        case 0:  conv_part<1, 128>(x, w0, b0, 0,  0,   smem); break;
        case 1:  conv_part<2, 128>(x, w1, b1, 0,  128, smem); break;
        case 2:  conv_part<3, 64> (x, w2, b2, 0,  256, smem); break;
        default: conv_part<3, 64> (x, w2, b2, 64, 320, smem); break;
    }
}

// ---------------- linear + tanh ----------------
// One CTA handles 16 rows of P. Weights [n][k] in SMEM with stride-385 padding
// (scalar reads conflict-free), P staged transposed [k][i16] for vectorized
// broadcast loads; i-pairs packed into FFMA2.
__global__ void __launch_bounds__(NT2, 1) k_lin(
    const float* __restrict__ lw, const float* __restrict__ lb,
    float* __restrict__ out)
{
    extern __shared__ float smem[];
    float* ws  = smem;               // [128][385]
    float* psT = smem + 128 * 385;   // [384][16]
    int tid = threadIdx.x;
    int i0  = blockIdx.x * 16;

    for (int idx = tid; idx < 128 * 384; idx += NT2) {
        int n = idx / 384; int k = idx - n * 384;
        ws[n * 385 + k] = lw[idx];
    }
    for (int idx = tid; idx < 16 * 384; idx += NT2) {
        int i = idx / 384; int k = idx - i * 384;
        psT[k * 16 + i] = g_P[(size_t)(i0 + i) * 384 + k];
    }
    __syncthreads();

    int n = tid;
    ull acc[8];
#pragma unroll
    for (int p = 0; p < 8; p++) acc[p] = 0ull;
    const float* wr = ws + n * 385;
#pragma unroll 4
    for (int k = 0; k < 384; k++) {
        float wv = wr[k];
        ull wp; asm("mov.b64 %0, {%1, %1};" : "=l"(wp) : "f"(wv));
        const ulonglong2* pp = (const ulonglong2*)&psT[k * 16];
        fma2(acc[0], pp[0].x, wp); fma2(acc[1], pp[0].y, wp);
        fma2(acc[2], pp[1].x, wp); fma2(acc[3], pp[1].y, wp);
        fma2(acc[4], pp[2].x, wp); fma2(acc[5], pp[2].y, wp);
        fma2(acc[6], pp[3].x, wp); fma2(acc[7], pp[3].y, wp);
    }
    float bias = lb[n];
#pragma unroll
    for (int p = 0; p < 8; p++) {
        F2U u; u.u = acc[p];
        out[(size_t)(i0 + 2 * p)     * 128 + n] = tanhf(u.f.x + bias);
        out[(size_t)(i0 + 2 * p + 1) * 128 + n] = tanhf(u.f.y + bias);
    }
}

// ---------------- launch ----------------
extern "C" void kernel_launch(void* const* d_in, const int* in_sizes, int n_in,
                              void* d_out, int out_size) {
    const float* x     = (const float*)d_in[0];
    const int*   sizes = (const int*)  d_in[1];
    const float* w0    = (const float*)d_in[2];
    const float* b0    = (const float*)d_in[3];
    const float* w1    = (const float*)d_in[4];
    const float* b1    = (const float*)d_in[5];
    const float* w2    = (const float*)d_in[6];
    const float* b2    = (const float*)d_in[7];
    const float* lw    = (const float*)d_in[8];
    const float* lb    = (const float*)d_in[9];
    float* out = (float*)d_out;

    const int SMEM1 = (70 * 128 + 128 * (2 * 128 + 4)) * 4;   // 168960
    const int SMEM2 = (128 * 385 + 384 * 16) * 4;             // 221696
    cudaFuncSetAttribute(k_conv, cudaFuncAttributeMaxDynamicSharedMemorySize, SMEM1);
    cudaFuncSetAttribute(k_lin,  cudaFuncAttributeMaxDynamicSharedMemorySize, SMEM2);

    k_scan<<<1, 1024>>>(sizes);
    dim3 g1(4, BATCH);
    k_conv<<<g1, NT1, SMEM1>>>(x, w0, b0, w1, b1, w2, b2);
    k_lin<<<BATCH / 16, NT2, SMEM2>>>(lw, lb, out);
}